// round 5
// baseline (speedup 1.0000x reference)
#include <cuda_runtime.h>
#include <cstdint>

// ============================================================
// 3-layer SNN. B=16384, H=512, 127 steps.
// h0 = relu_concat(x) @ W0 time-invariant (once, fp32 SIMT).
// Per step: spk0@W1 + LIF -> spk1 ; spk1@W2 + LIF -> m2 (+ fused layer-0 LIF).
// R5 engine: mma.sync m16n8k32 s8.s32 (IMMA). W split into 4 exact int8
// levels (scales 8, 1024, 2^17, 2^24); spikes {0,1} exact int8; s32
// accumulation exact; fp32 combine => ~1e-7 h error. 1.5x less tensor work
// than the 3x bf16 split.
// ============================================================

constexpr int NSTEP = 127;
#define NELEM (16384 * 512)

__device__ float g_h0[NELEM];
__device__ float g_m0[NELEM];
__device__ float g_s1[NELEM];
__device__ float g_m1[NELEM];
__device__ float g_s2[NELEM];
__device__ int8_t g_spk0[NELEM];
__device__ int8_t g_spk1[NELEM];
__device__ int8_t g_W1q[4][512 * 512];   // [split][N][K] K-contiguous
__device__ int8_t g_W2q[4][512 * 512];

// ---- PTX helpers (sm_80-class, valid at sm_103 base target) ----
__device__ __forceinline__ uint32_t smem_to_u32(const void* p) {
    uint32_t a;
    asm("{ .reg .u64 t; cvta.to.shared.u64 t, %1; cvt.u32.u64 %0, t; }"
        : "=r"(a) : "l"(p));
    return a;
}
__device__ __forceinline__ void cp16(uint32_t dst, const void* src) {
    asm volatile("cp.async.cg.shared.global [%0], [%1], 16;"
                 :: "r"(dst), "l"(src) : "memory");
}
#define CP_COMMIT() asm volatile("cp.async.commit_group;" ::: "memory")
#define CP_WAIT(N)  asm volatile("cp.async.wait_group %0;" :: "n"(N) : "memory")

__device__ __forceinline__ void ldm4(uint32_t& r0, uint32_t& r1, uint32_t& r2,
                                     uint32_t& r3, uint32_t addr) {
    asm volatile("ldmatrix.sync.aligned.m8n8.x4.shared.b16 {%0,%1,%2,%3}, [%4];"
                 : "=r"(r0), "=r"(r1), "=r"(r2), "=r"(r3) : "r"(addr));
}
__device__ __forceinline__ void imma16832(int* c, const uint32_t* a,
                                          uint32_t b0, uint32_t b1) {
    asm volatile(
        "mma.sync.aligned.m16n8k32.row.col.s32.s8.s8.s32 "
        "{%0,%1,%2,%3}, {%4,%5,%6,%7}, {%8,%9}, {%0,%1,%2,%3};"
        : "+r"(c[0]), "+r"(c[1]), "+r"(c[2]), "+r"(c[3])
        : "r"(a[0]), "r"(a[1]), "r"(a[2]), "r"(a[3]), "r"(b0), "r"(b1));
}
// 32B-row swizzle: 8 consecutive rows touch disjoint bank groups
__device__ __forceinline__ uint32_t swz32(int row, int h) {
    return (uint32_t)(row * 32 + ((h ^ ((row >> 2) & 1)) << 4));
}

// ============================================================
// one-time kernels
// ============================================================
__global__ void zero_kernel(float4* __restrict__ out) {
    int i = blockIdx.x * blockDim.x + threadIdx.x;
    float4 z = make_float4(0.f, 0.f, 0.f, 0.f);
    ((float4*)g_m0)[i] = z;
    ((float4*)g_s1)[i] = z;
    ((float4*)g_m1)[i] = z;
    ((float4*)g_s2)[i] = z;
    out[i] = z;
}

// exact 4-level int8 split + transpose: W[k][n] -> Wq[sp][n][k]
template <int WHICH>
__global__ void prep_q(const float* __restrict__ Wsrc) {
    int idx = blockIdx.x * blockDim.x + threadIdx.x;  // over 512*512
    int k = idx >> 9, n = idx & 511;
    float r = Wsrc[idx];
    const float s[4]   = {8.f, 1024.f, 131072.f, 16777216.f};
    const float inv[4] = {0.125f, 1.f / 1024.f, 1.f / 131072.f, 1.f / 16777216.f};
    int8_t (*dst)[512 * 512] = (WHICH == 1) ? g_W1q : g_W2q;
    int t = n * 512 + k;
#pragma unroll
    for (int j = 0; j < 4; j++) {
        float qf = rintf(r * s[j]);
        qf = fminf(fmaxf(qf, -127.f), 127.f);
        dst[j][t] = (int8_t)qf;
        r -= qf * inv[j];               // exact (power-of-2 scale, Sterbenz)
    }
}

// standalone layer-0 LIF (t=0 only; later fused into gemm_i8<2>)
__global__ void step0_kernel() {
    int i = blockIdx.x * blockDim.x + threadIdx.x;
    float4 h = ((const float4*)g_h0)[i];
    float4 m = ((const float4*)g_m0)[i];
    m.x = 0.85f * m.x + h.x;  m.y = 0.85f * m.y + h.y;
    m.z = 0.85f * m.z + h.z;  m.w = 0.85f * m.w + h.w;
    char4 s;
    s.x = (m.x > 1.f) ? 1 : 0;  m.x = (m.x > 1.f) ? 0.f : m.x;
    s.y = (m.y > 1.f) ? 1 : 0;  m.y = (m.y > 1.f) ? 0.f : m.y;
    s.z = (m.z > 1.f) ? 1 : 0;  m.z = (m.z > 1.f) ? 0.f : m.z;
    s.w = (m.w > 1.f) ? 1 : 0;  m.w = (m.w > 1.f) ? 0.f : m.w;
    ((float4*)g_m0)[i] = m;
    ((char4*)g_spk0)[i] = s;
}

// ============================================================
// layer-0 drive: h0 = relu_concat(inputs) @ W0 (fp32, runs once)
// ============================================================
__global__ __launch_bounds__(256)
void gemm0_kernel(const float* __restrict__ Aext, const float* __restrict__ W) {
    constexpr int KT = 8, NK = 256 / KT;
    __shared__ float As[2][KT][128];
    __shared__ float Bs[2][KT][128];
    const int row0 = blockIdx.x * 128, col0 = blockIdx.y * 128;
    const int tid = threadIdx.x;
    const int tx = tid & 15, ty = tid >> 4;
    const int ar = tid >> 1, aq = (tid & 1) * 4;
    const int bk = tid >> 5, bj = (tid & 31) * 4;

    float acc[8][8];
#pragma unroll
    for (int i = 0; i < 8; i++)
#pragma unroll
        for (int j = 0; j < 8; j++) acc[i][j] = 0.f;

    float4 ra, rb;
    auto LOADG = [&](int k0) {
        int kk = k0 + aq;
        if (kk < 128) {
            float4 v = *(const float4*)(Aext + (size_t)(row0 + ar) * 128 + kk);
            ra.x = fmaxf(v.x, 0.f); ra.y = fmaxf(v.y, 0.f);
            ra.z = fmaxf(v.z, 0.f); ra.w = fmaxf(v.w, 0.f);
        } else {
            float4 v = *(const float4*)(Aext + (size_t)(row0 + ar) * 128 + (kk - 128));
            ra.x = fmaxf(-v.x, 0.f); ra.y = fmaxf(-v.y, 0.f);
            ra.z = fmaxf(-v.z, 0.f); ra.w = fmaxf(-v.w, 0.f);
        }
        rb = *(const float4*)(W + (size_t)(k0 + bk) * 512 + col0 + bj);
    };
    auto STORES = [&](int buf) {
        As[buf][aq + 0][ar] = ra.x; As[buf][aq + 1][ar] = ra.y;
        As[buf][aq + 2][ar] = ra.z; As[buf][aq + 3][ar] = ra.w;
        *(float4*)&Bs[buf][bk][bj] = rb;
    };

    LOADG(0); STORES(0); __syncthreads();
    for (int kt = 0; kt < NK; kt++) {
        const int buf = kt & 1;
        if (kt + 1 < NK) LOADG((kt + 1) * KT);
#pragma unroll
        for (int k = 0; k < KT; k++) {
            float4 a0 = *(const float4*)&As[buf][k][ty * 8];
            float4 a1 = *(const float4*)&As[buf][k][ty * 8 + 4];
            float4 b0 = *(const float4*)&Bs[buf][k][tx * 8];
            float4 b1 = *(const float4*)&Bs[buf][k][tx * 8 + 4];
            float av[8] = {a0.x, a0.y, a0.z, a0.w, a1.x, a1.y, a1.z, a1.w};
            float bv[8] = {b0.x, b0.y, b0.z, b0.w, b1.x, b1.y, b1.z, b1.w};
#pragma unroll
            for (int i = 0; i < 8; i++)
#pragma unroll
                for (int j = 0; j < 8; j++) acc[i][j] = fmaf(av[i], bv[j], acc[i][j]);
        }
        if (kt + 1 < NK) STORES(buf ^ 1);
        __syncthreads();
    }
    const int r0 = row0 + ty * 8, c0 = col0 + tx * 8;
#pragma unroll
    for (int i = 0; i < 8; i++) {
        size_t base = (size_t)(r0 + i) * 512 + c0;
        *(float4*)&g_h0[base]     = make_float4(acc[i][0], acc[i][1], acc[i][2], acc[i][3]);
        *(float4*)&g_h0[base + 4] = make_float4(acc[i][4], acc[i][5], acc[i][6], acc[i][7]);
    }
}

// ============================================================
// IMMA GEMM + fused LIF epilogue
// CTA: 128 rows x 256 cols (4 N-tiles of 64), 256 threads, 8 warps (4m x 2n),
// warp tile 32x32. A (spikes int8, 128x512 = 64KB) resident in smem.
// B streamed: 64 chunks (4 nt x 4 split x 4 kc) of [4 kpanels][64n][32B],
// 8KB each, 3-stage cp.async pipeline. acc s32 per split, drained into fp32 h.
// Grid 128 x 2 = 256 CTAs (balanced, all resident).
// ============================================================
constexpr int B_CH      = 8192;
constexpr int SMEM_NEED = 65536 + 3 * B_CH;     // 88KB -> 2 CTAs/SM

template <int MODE>
__global__ __launch_bounds__(256, 2)
void gemm_i8(float* __restrict__ Mext) {
    extern __shared__ char smem[];
    const int tid = threadIdx.x;
    const int wid = tid >> 5, lane = tid & 31;
    const int warp_m = wid & 3, warp_n = wid >> 2;
    const int mat = lane >> 3, mrr = lane & 7;
    const int row0 = blockIdx.x * 128;
    const int nh   = blockIdx.y;                 // cols [nh*256, nh*256+256)

    const int8_t* A  = (MODE == 1) ? g_spk0 : g_spk1;
    const int8_t* Wq = (MODE == 1) ? &g_W1q[0][0] : &g_W2q[0][0];

    const uint32_t sb = smem_to_u32(smem);
    const uint32_t ap = sb;                      // A: 16 kpanels x [128][32B]
    const uint32_t bp = sb + 65536;              // B: 3 stages x 8KB

    // ---- resident A: 128 rows x 512 K int8 ----
#pragma unroll
    for (int j = 0; j < 16; j++) {
        int v = tid + j * 256;                   // 4096 x 16B segs
        int g = v >> 8, rem = v & 255;
        int r = rem >> 1, h = rem & 1;
        cp16(ap + g * 4096 + swz32(r, h),
             A + (size_t)(row0 + r) * 512 + g * 32 + h * 16);
    }

    // ---- B chunk loader: chunk g -> (nt, sp, kc) ----
    auto load_B = [&](int g) {
        int nt = g >> 4, sp = (g >> 2) & 3, kc = g & 3;
        const int c0 = nh * 256 + nt * 64;
        const uint32_t dst = bp + (g % 3) * B_CH;
#pragma unroll
        for (int j = 0; j < 2; j++) {            // 512 x 16B segs
            int v = tid + j * 256;
            int p = v >> 7, rem = v & 127;
            int n = rem >> 1, h = rem & 1;
            cp16(dst + p * 2048 + swz32(n, h),
                 Wq + (size_t)sp * 262144 + (size_t)(c0 + n) * 512 +
                     kc * 128 + p * 32 + h * 16);
        }
        CP_COMMIT();
    };

    load_B(0);                                   // group 0 = A + chunk 0
    load_B(1);

    // ---- MODE 2: layer-0 LIF for next step (overlaps pipeline fill) ----
    if (MODE == 2) {
#pragma unroll
        for (int j = 0; j < 32; j++) {
            int v = tid + j * 256;               // 8192 float4 groups
            int rr = v >> 6, cc = (v & 63) << 2;
            size_t ix = (size_t)(row0 + rr) * 512 + nh * 256 + cc;
            float4 h = *(const float4*)(g_h0 + ix);
            float4 m = *(const float4*)(g_m0 + ix);
            m.x = 0.85f * m.x + h.x;  m.y = 0.85f * m.y + h.y;
            m.z = 0.85f * m.z + h.z;  m.w = 0.85f * m.w + h.w;
            char4 s;
            s.x = (m.x > 1.f) ? 1 : 0;  m.x = (m.x > 1.f) ? 0.f : m.x;
            s.y = (m.y > 1.f) ? 1 : 0;  m.y = (m.y > 1.f) ? 0.f : m.y;
            s.z = (m.z > 1.f) ? 1 : 0;  m.z = (m.z > 1.f) ? 0.f : m.z;
            s.w = (m.w > 1.f) ? 1 : 0;  m.w = (m.w > 1.f) ? 0.f : m.w;
            *(float4*)(g_m0 + ix) = m;
            *(char4*)(g_spk0 + ix) = s;
        }
    }

    int gl = 2;
    const int arow = warp_m * 32 + (mat & 1) * 8 + mrr;   // + mt*16
    const int ah   = mat >> 1;
    const int brow = warp_n * 32 + ((mat >> 1) & 1) * 8 + mrr;  // + t*16
    const int bh   = mat & 1;

#pragma unroll 1
    for (int nt = 0; nt < 4; nt++) {
        float h[2][4][4];
#pragma unroll
        for (int mt = 0; mt < 2; mt++)
#pragma unroll
            for (int nb = 0; nb < 4; nb++)
#pragma unroll
                for (int e = 0; e < 4; e++) h[mt][nb][e] = 0.f;

#pragma unroll 1
        for (int sp = 0; sp < 4; sp++) {
            int acc[2][4][4];
#pragma unroll
            for (int mt = 0; mt < 2; mt++)
#pragma unroll
                for (int nb = 0; nb < 4; nb++)
#pragma unroll
                    for (int e = 0; e < 4; e++) acc[mt][nb][e] = 0;

#pragma unroll 1
            for (int kc = 0; kc < 4; kc++) {
                const int g = nt * 16 + sp * 4 + kc;
                if (g < 63) CP_WAIT(1); else CP_WAIT(0);
                __syncthreads();
                if (gl < 64) { load_B(gl); gl++; }

                const uint32_t bstage = bp + (g % 3) * B_CH;
#pragma unroll
                for (int p = 0; p < 4; p++) {
                    const uint32_t apan = ap + (kc * 4 + p) * 4096;
                    uint32_t a[2][4];
#pragma unroll
                    for (int mt = 0; mt < 2; mt++)
                        ldm4(a[mt][0], a[mt][1], a[mt][2], a[mt][3],
                             apan + swz32(arow + mt * 16, ah));
                    uint32_t b[2][4];
#pragma unroll
                    for (int t = 0; t < 2; t++)
                        ldm4(b[t][0], b[t][1], b[t][2], b[t][3],
                             bstage + p * 2048 + swz32(brow + t * 16, bh));
#pragma unroll
                    for (int mt = 0; mt < 2; mt++)
#pragma unroll
                        for (int nb = 0; nb < 4; nb++)
                            imma16832(acc[mt][nb], a[mt],
                                      b[nb >> 1][(nb & 1) * 2],
                                      b[nb >> 1][(nb & 1) * 2 + 1]);
                }
                __syncthreads();
            }

            // drain: h += c_sp * acc  (acc exact s32, < 2^24)
            const float cs = (sp == 0) ? 0.125f
                           : (sp == 1) ? 9.765625e-4f
                           : (sp == 2) ? 7.62939453125e-6f
                                       : 5.9604644775390625e-8f;
#pragma unroll
            for (int mt = 0; mt < 2; mt++)
#pragma unroll
                for (int nb = 0; nb < 4; nb++)
#pragma unroll
                    for (int e = 0; e < 4; e++)
                        h[mt][nb][e] += cs * (float)acc[mt][nb][e];
        }

        // ---- fused LIF epilogue for this N-tile ----
        float* S = (MODE == 1) ? g_s1 : g_s2;
        float* M = (MODE == 1) ? g_m1 : Mext;
        const int er = row0 + warp_m * 32 + (lane >> 2);
        const int ec = nh * 256 + nt * 64 + warp_n * 32 + (lane & 3) * 2;
#pragma unroll
        for (int mt = 0; mt < 2; mt++)
#pragma unroll
            for (int nb = 0; nb < 4; nb++)
#pragma unroll
                for (int hrow = 0; hrow < 2; hrow++) {
                    size_t ix = (size_t)(er + mt * 16 + hrow * 8) * 512 + ec + nb * 8;
                    float2 sv = *(const float2*)(S + ix);
                    float2 mv = *(const float2*)(M + ix);
                    sv.x = 0.9f * sv.x + h[mt][nb][hrow * 2 + 0];
                    mv.x = 0.85f * mv.x + sv.x;
                    sv.y = 0.9f * sv.y + h[mt][nb][hrow * 2 + 1];
                    mv.y = 0.85f * mv.y + sv.y;
                    if (MODE == 1) {
                        char2 pk;
                        pk.x = (mv.x > 1.f) ? 1 : 0;  mv.x = (mv.x > 1.f) ? 0.f : mv.x;
                        pk.y = (mv.y > 1.f) ? 1 : 0;  mv.y = (mv.y > 1.f) ? 0.f : mv.y;
                        *(char2*)(g_spk1 + ix) = pk;
                    }
                    *(float2*)(S + ix) = sv;
                    *(float2*)(M + ix) = mv;
                }
    }
}

// ============================================================
// launch
// ============================================================
extern "C" void kernel_launch(void* const* d_in, const int* in_sizes, int n_in,
                              void* d_out, int out_size) {
    (void)in_sizes; (void)n_in; (void)out_size;
    const float* inp = (const float*)d_in[0];   // [16384, 128]
    const float* W0  = (const float*)d_in[1];   // [256, 512]
    const float* W1  = (const float*)d_in[2];   // [512, 512]
    const float* W2  = (const float*)d_in[3];   // [512, 512]
    float* out = (float*)d_out;                 // m2 state [16384, 512]

    cudaFuncSetAttribute(gemm_i8<1>, cudaFuncAttributeMaxDynamicSharedMemorySize, SMEM_NEED);
    cudaFuncSetAttribute(gemm_i8<2>, cudaFuncAttributeMaxDynamicSharedMemorySize, SMEM_NEED);

    const int EW_BLOCKS = (NELEM / 4) / 256;    // 8192

    zero_kernel<<<EW_BLOCKS, 256>>>((float4*)out);
    prep_q<1><<<1024, 256>>>(W1);
    prep_q<2><<<1024, 256>>>(W2);
    gemm0_kernel<<<dim3(128, 4), 256>>>(inp, W0);
    step0_kernel<<<EW_BLOCKS, 256>>>();

    dim3 grid(128, 2);
    for (int t = 0; t < NSTEP; t++) {
        gemm_i8<1><<<grid, 256, SMEM_NEED>>>(nullptr);
        gemm_i8<2><<<grid, 256, SMEM_NEED>>>(out);
    }
}

// round 6
// speedup vs baseline: 3.0161x; 3.0161x over previous
#include <cuda_runtime.h>
#include <cuda_bf16.h>
#include <cstdint>

// ============================================================
// 3-layer SNN. B=16384, H=512, 127 steps.
// h0 = relu_concat(x) @ W0 time-invariant (once, fp32 SIMT).
// Per step: spk0@W1 + LIF -> spk1 ; spk1@W2 + LIF -> m2 (+ fused layer-0 LIF).
// Engine: mma.sync m16n8k16 bf16 HMMA, exact 3-way bf16 split of W.
// R6: warp tile 64x32 (2m x 4n) -> 10 ldm4 / 48 mma per k16 (was 14/48):
// cuts smem crossbar traffic ~29%, which the cycle model says is the binding
// resource. (INT8 path reverted: B300 cut dense IMMA rate.)
// ============================================================

constexpr int BATCH = 16384;
constexpr int NSTEP = 127;
#define NELEM (16384 * 512)

__device__ float g_h0[NELEM];
__device__ float g_m0[NELEM];
__device__ float g_s1[NELEM];
__device__ float g_m1[NELEM];
__device__ float g_s2[NELEM];
__device__ __nv_bfloat16 g_spk0[NELEM];
__device__ __nv_bfloat16 g_spk1[NELEM];
__device__ __nv_bfloat16 g_W1t[3][512 * 512];   // [split][N][K] K-contiguous
__device__ __nv_bfloat16 g_W2t[3][512 * 512];

// ---- PTX helpers (sm_80-class, valid at sm_103 base target) ----
__device__ __forceinline__ uint32_t smem_to_u32(const void* p) {
    uint32_t a;
    asm("{ .reg .u64 t; cvta.to.shared.u64 t, %1; cvt.u32.u64 %0, t; }"
        : "=r"(a) : "l"(p));
    return a;
}
__device__ __forceinline__ void cp16(uint32_t dst, const void* src) {
    asm volatile("cp.async.cg.shared.global [%0], [%1], 16;"
                 :: "r"(dst), "l"(src) : "memory");
}
#define CP_COMMIT() asm volatile("cp.async.commit_group;" ::: "memory")
#define CP_WAIT(N)  asm volatile("cp.async.wait_group %0;" :: "n"(N) : "memory")

__device__ __forceinline__ void ldm4(uint32_t& r0, uint32_t& r1, uint32_t& r2,
                                     uint32_t& r3, uint32_t addr) {
    asm volatile("ldmatrix.sync.aligned.m8n8.x4.shared.b16 {%0,%1,%2,%3}, [%4];"
                 : "=r"(r0), "=r"(r1), "=r"(r2), "=r"(r3) : "r"(addr));
}
__device__ __forceinline__ void mma16816(float* c, const uint32_t* a,
                                         uint32_t b0, uint32_t b1) {
    asm volatile(
        "mma.sync.aligned.m16n8k16.row.col.f32.bf16.bf16.f32 "
        "{%0,%1,%2,%3}, {%4,%5,%6,%7}, {%8,%9}, {%0,%1,%2,%3};"
        : "+f"(c[0]), "+f"(c[1]), "+f"(c[2]), "+f"(c[3])
        : "r"(a[0]), "r"(a[1]), "r"(a[2]), "r"(a[3]), "r"(b0), "r"(b1));
}
// SW64 swizzle for 64-byte rows (8 rows x 64B atom): conflict-free ldmatrix
#define SWZ64(x) ((x) ^ (((x) >> 3) & 0x30))

// ============================================================
// one-time kernels
// ============================================================
__global__ void zero_kernel(float4* __restrict__ out) {
    int i = blockIdx.x * blockDim.x + threadIdx.x;
    float4 z = make_float4(0.f, 0.f, 0.f, 0.f);
    ((float4*)g_m0)[i] = z;
    ((float4*)g_s1)[i] = z;
    ((float4*)g_m1)[i] = z;
    ((float4*)g_s2)[i] = z;
    out[i] = z;
}

template <int WHICH>
__global__ void prep_kernel(const float* __restrict__ Wsrc) {
    int idx = blockIdx.x * blockDim.x + threadIdx.x;  // over 512*512
    int k = idx >> 9, n = idx & 511;
    float w = Wsrc[idx];
    __nv_bfloat16 hi = __float2bfloat16(w);
    float r1 = w - __bfloat162float(hi);
    __nv_bfloat16 mid = __float2bfloat16(r1);
    float r2 = r1 - __bfloat162float(mid);
    __nv_bfloat16 lo = __float2bfloat16(r2);
    __nv_bfloat16 (*dst)[512 * 512] = (WHICH == 1) ? g_W1t : g_W2t;
    int t = n * 512 + k;
    dst[0][t] = hi;
    dst[1][t] = mid;
    dst[2][t] = lo;
}

__global__ void step0_kernel() {
    int i = blockIdx.x * blockDim.x + threadIdx.x;
    float4 h = ((const float4*)g_h0)[i];
    float4 m = ((const float4*)g_m0)[i];
    m.x = 0.85f * m.x + h.x;  m.y = 0.85f * m.y + h.y;
    m.z = 0.85f * m.z + h.z;  m.w = 0.85f * m.w + h.w;
    float sx = (m.x > 1.f) ? 1.f : 0.f;  m.x = (m.x > 1.f) ? 0.f : m.x;
    float sy = (m.y > 1.f) ? 1.f : 0.f;  m.y = (m.y > 1.f) ? 0.f : m.y;
    float sz = (m.z > 1.f) ? 1.f : 0.f;  m.z = (m.z > 1.f) ? 0.f : m.z;
    float sw = (m.w > 1.f) ? 1.f : 0.f;  m.w = (m.w > 1.f) ? 0.f : m.w;
    ((float4*)g_m0)[i] = m;
    __nv_bfloat162* sp = (__nv_bfloat162*)(g_spk0 + 4 * (size_t)i);
    sp[0] = __floats2bfloat162_rn(sx, sy);
    sp[1] = __floats2bfloat162_rn(sz, sw);
}

// ============================================================
// layer-0 drive: h0 = relu_concat(inputs) @ W0 (fp32, runs once)
// ============================================================
__global__ __launch_bounds__(256)
void gemm0_kernel(const float* __restrict__ Aext, const float* __restrict__ W) {
    constexpr int KT = 8, NK = 256 / KT;
    __shared__ float As[2][KT][128];
    __shared__ float Bs[2][KT][128];
    const int row0 = blockIdx.x * 128, col0 = blockIdx.y * 128;
    const int tid = threadIdx.x;
    const int tx = tid & 15, ty = tid >> 4;
    const int ar = tid >> 1, aq = (tid & 1) * 4;
    const int bk = tid >> 5, bj = (tid & 31) * 4;

    float acc[8][8];
#pragma unroll
    for (int i = 0; i < 8; i++)
#pragma unroll
        for (int j = 0; j < 8; j++) acc[i][j] = 0.f;

    float4 ra, rb;
    auto LOADG = [&](int k0) {
        int kk = k0 + aq;
        if (kk < 128) {
            float4 v = *(const float4*)(Aext + (size_t)(row0 + ar) * 128 + kk);
            ra.x = fmaxf(v.x, 0.f); ra.y = fmaxf(v.y, 0.f);
            ra.z = fmaxf(v.z, 0.f); ra.w = fmaxf(v.w, 0.f);
        } else {
            float4 v = *(const float4*)(Aext + (size_t)(row0 + ar) * 128 + (kk - 128));
            ra.x = fmaxf(-v.x, 0.f); ra.y = fmaxf(-v.y, 0.f);
            ra.z = fmaxf(-v.z, 0.f); ra.w = fmaxf(-v.w, 0.f);
        }
        rb = *(const float4*)(W + (size_t)(k0 + bk) * 512 + col0 + bj);
    };
    auto STORES = [&](int buf) {
        As[buf][aq + 0][ar] = ra.x; As[buf][aq + 1][ar] = ra.y;
        As[buf][aq + 2][ar] = ra.z; As[buf][aq + 3][ar] = ra.w;
        *(float4*)&Bs[buf][bk][bj] = rb;
    };

    LOADG(0); STORES(0); __syncthreads();
    for (int kt = 0; kt < NK; kt++) {
        const int buf = kt & 1;
        if (kt + 1 < NK) LOADG((kt + 1) * KT);
#pragma unroll
        for (int k = 0; k < KT; k++) {
            float4 a0 = *(const float4*)&As[buf][k][ty * 8];
            float4 a1 = *(const float4*)&As[buf][k][ty * 8 + 4];
            float4 b0 = *(const float4*)&Bs[buf][k][tx * 8];
            float4 b1 = *(const float4*)&Bs[buf][k][tx * 8 + 4];
            float av[8] = {a0.x, a0.y, a0.z, a0.w, a1.x, a1.y, a1.z, a1.w};
            float bv[8] = {b0.x, b0.y, b0.z, b0.w, b1.x, b1.y, b1.z, b1.w};
#pragma unroll
            for (int i = 0; i < 8; i++)
#pragma unroll
                for (int j = 0; j < 8; j++) acc[i][j] = fmaf(av[i], bv[j], acc[i][j]);
        }
        if (kt + 1 < NK) STORES(buf ^ 1);
        __syncthreads();
    }
    const int r0 = row0 + ty * 8, c0 = col0 + tx * 8;
#pragma unroll
    for (int i = 0; i < 8; i++) {
        size_t base = (size_t)(r0 + i) * 512 + c0;
        *(float4*)&g_h0[base]     = make_float4(acc[i][0], acc[i][1], acc[i][2], acc[i][3]);
        *(float4*)&g_h0[base + 4] = make_float4(acc[i][4], acc[i][5], acc[i][6], acc[i][7]);
    }
}

// ============================================================
// HMMA GEMM + fused LIF epilogue (register-direct)
// Tile M=128 x N=128; K=512 in 16 chunks of 32; 3 bf16 W-splits.
// 3-stage cp.async pipeline, 32KB/stage (A 8KB + B 3x8KB), SW64 swizzle.
// 8 warps, warp tile 64x32: warp_m = wid&1, warp_n = wid>>1.
// ============================================================
constexpr int STAGE_BYTES = 32768;
constexpr int SMEM_NEED   = 3 * STAGE_BYTES;   // 96KB -> 2 CTAs/SM

template <int MODE>
__global__ __launch_bounds__(256, 2)
void gemm_mma(float* __restrict__ Mext) {
    extern __shared__ char smem[];
    const int tid = threadIdx.x;
    const int wid = tid >> 5, lane = tid & 31;
    const int warp_m = wid & 1, warp_n = wid >> 1;
    const int row0 = blockIdx.x * 128, col0 = blockIdx.y * 128;

    const __nv_bfloat16* A = (MODE == 1) ? g_spk0 : g_spk1;
    const __nv_bfloat16* W = (MODE == 1) ? &g_W1t[0][0] : &g_W2t[0][0];

    const uint32_t sb = smem_to_u32(smem);

    // ---- async chunk staging: A[128r][32k], B[3][128n][32k], SW64 ----
    auto load_chunk = [&](int c, int s) {
        const uint32_t ap = sb + s * STAGE_BYTES;
        const uint32_t bp = ap + 8192;
        const int k0 = c * 32;
#pragma unroll
        for (int j = 0; j < 2; j++) {                  // A: 512 x 16B
            int i = tid + j * 256;
            int r = i >> 2, q = i & 3;
            cp16(ap + SWZ64(r * 64 + q * 16),
                 A + (size_t)(row0 + r) * 512 + k0 + q * 8);
        }
#pragma unroll
        for (int j = 0; j < 6; j++) {                  // B: 3 x 512 x 16B
            int i = tid + j * 256;
            int sp = i >> 9, rem = i & 511;
            int n = rem >> 2, q = rem & 3;
            cp16(bp + sp * 8192 + SWZ64(n * 64 + q * 16),
                 W + (size_t)sp * 262144 + (size_t)(col0 + n) * 512 + k0 + q * 8);
        }
        CP_COMMIT();
    };

    load_chunk(0, 0);
    load_chunk(1, 1);

    // ---- MODE 2: layer-0 LIF for NEXT step (overlaps pipeline fill) ----
    if (MODE == 2) {
#pragma unroll
        for (int j = 0; j < 16; j++) {
            int v = tid + j * 256;
            int rr = v >> 5, cc = (v & 31) << 2;
            size_t ix = (size_t)(row0 + rr) * 512 + col0 + cc;
            float4 h = *(const float4*)(g_h0 + ix);
            float4 m = *(const float4*)(g_m0 + ix);
            m.x = 0.85f * m.x + h.x;  m.y = 0.85f * m.y + h.y;
            m.z = 0.85f * m.z + h.z;  m.w = 0.85f * m.w + h.w;
            float px = (m.x > 1.f) ? 1.f : 0.f;  m.x = (m.x > 1.f) ? 0.f : m.x;
            float py = (m.y > 1.f) ? 1.f : 0.f;  m.y = (m.y > 1.f) ? 0.f : m.y;
            float pz = (m.z > 1.f) ? 1.f : 0.f;  m.z = (m.z > 1.f) ? 0.f : m.z;
            float pw = (m.w > 1.f) ? 1.f : 0.f;  m.w = (m.w > 1.f) ? 0.f : m.w;
            *(float4*)(g_m0 + ix) = m;
            __nv_bfloat162* sp2 = (__nv_bfloat162*)(g_spk0 + ix);
            sp2[0] = __floats2bfloat162_rn(px, py);
            sp2[1] = __floats2bfloat162_rn(pz, pw);
        }
    }

    float acc[4][4][4];
#pragma unroll
    for (int mt = 0; mt < 4; mt++)
#pragma unroll
        for (int nb = 0; nb < 4; nb++)
#pragma unroll
            for (int e = 0; e < 4; e++) acc[mt][nb][e] = 0.f;

    const int mat = lane >> 3, mrr = lane & 7;

#pragma unroll 1
    for (int c = 0; c < 16; c++) {
        const int s = c % 3;
        if (c < 15) CP_WAIT(1); else CP_WAIT(0);
        __syncthreads();
        if (c + 2 < 16) load_chunk(c + 2, (c + 2) % 3);

        const uint32_t ab = sb + s * STAGE_BYTES;
        const uint32_t bb = ab + 8192;
#pragma unroll
        for (int k16 = 0; k16 < 2; k16++) {
            const int k0 = k16 * 16;
            uint32_t a[4][4];
#pragma unroll
            for (int mt = 0; mt < 4; mt++) {
                int row = warp_m * 64 + mt * 16 + (mat & 1) * 8 + mrr;
                int kk  = k0 + (mat >> 1) * 8;
                ldm4(a[mt][0], a[mt][1], a[mt][2], a[mt][3],
                     ab + SWZ64(row * 64 + kk * 2));
            }
#pragma unroll
            for (int sp = 0; sp < 3; sp++) {
                uint32_t b[2][4];
#pragma unroll
                for (int nt = 0; nt < 2; nt++) {
                    int n  = warp_n * 32 + nt * 16 + (mat >> 1) * 8 + mrr;
                    int kk = k0 + (mat & 1) * 8;
                    ldm4(b[nt][0], b[nt][1], b[nt][2], b[nt][3],
                         bb + sp * 8192 + SWZ64(n * 64 + kk * 2));
                }
#pragma unroll
                for (int mt = 0; mt < 4; mt++)
#pragma unroll
                    for (int nb = 0; nb < 4; nb++)
                        mma16816(acc[mt][nb], a[mt],
                                 b[nb >> 1][(nb & 1) * 2],
                                 b[nb >> 1][(nb & 1) * 2 + 1]);
            }
        }
        __syncthreads();
    }

    // ---- fused LIF epilogue, direct from mma fragments ----
    float* S = (MODE == 1) ? g_s1 : g_s2;
    float* M = (MODE == 1) ? g_m1 : Mext;
    const int er = row0 + warp_m * 64 + (lane >> 2);
    const int ec = col0 + warp_n * 32 + (lane & 3) * 2;
#pragma unroll
    for (int mt = 0; mt < 4; mt++)
#pragma unroll
        for (int nb = 0; nb < 4; nb++)
#pragma unroll
            for (int hrow = 0; hrow < 2; hrow++) {
                size_t ix = (size_t)(er + mt * 16 + hrow * 8) * 512 + ec + nb * 8;
                float2 sv = *(const float2*)(S + ix);
                float2 mv = *(const float2*)(M + ix);
                float hx = acc[mt][nb][hrow * 2 + 0];
                float hy = acc[mt][nb][hrow * 2 + 1];
                sv.x = 0.9f * sv.x + hx;  mv.x = 0.85f * mv.x + sv.x;
                sv.y = 0.9f * sv.y + hy;  mv.y = 0.85f * mv.y + sv.y;
                if (MODE == 1) {
                    float px = (mv.x > 1.f) ? 1.f : 0.f;  mv.x = (mv.x > 1.f) ? 0.f : mv.x;
                    float py = (mv.y > 1.f) ? 1.f : 0.f;  mv.y = (mv.y > 1.f) ? 0.f : mv.y;
                    *(__nv_bfloat162*)(g_spk1 + ix) = __floats2bfloat162_rn(px, py);
                }
                *(float2*)(S + ix) = sv;
                *(float2*)(M + ix) = mv;
            }
}

// ============================================================
// launch
// ============================================================
extern "C" void kernel_launch(void* const* d_in, const int* in_sizes, int n_in,
                              void* d_out, int out_size) {
    (void)in_sizes; (void)n_in; (void)out_size;
    const float* inp = (const float*)d_in[0];   // [16384, 128]
    const float* W0  = (const float*)d_in[1];   // [256, 512]
    const float* W1  = (const float*)d_in[2];   // [512, 512]
    const float* W2  = (const float*)d_in[3];   // [512, 512]
    float* out = (float*)d_out;                 // m2 state [16384, 512]

    cudaFuncSetAttribute(gemm_mma<1>, cudaFuncAttributeMaxDynamicSharedMemorySize, SMEM_NEED);
    cudaFuncSetAttribute(gemm_mma<2>, cudaFuncAttributeMaxDynamicSharedMemorySize, SMEM_NEED);

    const int EW_BLOCKS = (NELEM / 4) / 256;    // 8192

    zero_kernel<<<EW_BLOCKS, 256>>>((float4*)out);
    prep_kernel<1><<<1024, 256>>>(W1);
    prep_kernel<2><<<1024, 256>>>(W2);
    gemm0_kernel<<<dim3(128, 4), 256>>>(inp, W0);
    step0_kernel<<<EW_BLOCKS, 256>>>();

    dim3 grid(128, 4);
    for (int t = 0; t < NSTEP; t++) {
        gemm_mma<1><<<grid, 256, SMEM_NEED>>>(nullptr);
        gemm_mma<2><<<grid, 256, SMEM_NEED>>>(out);
    }
}

// round 7
// speedup vs baseline: 3.4922x; 1.1579x over previous
#include <cuda_runtime.h>
#include <cuda_fp16.h>
#include <cstdint>

// ============================================================
// 3-layer SNN. B=16384, H=512, 127 steps.
// h0 = relu_concat(x) @ W0 time-invariant (once, fp32 SIMT).
// Per step: spk0@W1 + LIF -> spk1 ; spk1@W2 + LIF -> m2 (+ fused layer-0 LIF).
// Engine: mma.sync m16n8k16 fp16 HMMA (sm_103 runs legacy mma at ~512
// MAC/cyc/SM — issue-bound), W split into 2 exact fp16 levels:
//   hi = fp16(w), lo = fp16(w - hi), residual <= 2^-22|w|.
// Spikes {0,1} exact in fp16; fp32 accumulate. 2/3 the tensor work of the
// 3-way bf16 split at nearly the same precision.
// ============================================================

constexpr int NSTEP = 127;
#define NELEM (16384 * 512)

__device__ float g_h0[NELEM];
__device__ float g_m0[NELEM];
__device__ float g_s1[NELEM];
__device__ float g_m1[NELEM];
__device__ float g_s2[NELEM];
__device__ __half g_spk0[NELEM];
__device__ __half g_spk1[NELEM];
__device__ __half g_W1t[2][512 * 512];   // [split][N][K] K-contiguous
__device__ __half g_W2t[2][512 * 512];

// ---- PTX helpers (sm_80-class, valid at sm_103 base target) ----
__device__ __forceinline__ uint32_t smem_to_u32(const void* p) {
    uint32_t a;
    asm("{ .reg .u64 t; cvta.to.shared.u64 t, %1; cvt.u32.u64 %0, t; }"
        : "=r"(a) : "l"(p));
    return a;
}
__device__ __forceinline__ void cp16(uint32_t dst, const void* src) {
    asm volatile("cp.async.cg.shared.global [%0], [%1], 16;"
                 :: "r"(dst), "l"(src) : "memory");
}
#define CP_COMMIT() asm volatile("cp.async.commit_group;" ::: "memory")
#define CP_WAIT(N)  asm volatile("cp.async.wait_group %0;" :: "n"(N) : "memory")

__device__ __forceinline__ void ldm4(uint32_t& r0, uint32_t& r1, uint32_t& r2,
                                     uint32_t& r3, uint32_t addr) {
    asm volatile("ldmatrix.sync.aligned.m8n8.x4.shared.b16 {%0,%1,%2,%3}, [%4];"
                 : "=r"(r0), "=r"(r1), "=r"(r2), "=r"(r3) : "r"(addr));
}
__device__ __forceinline__ void mma16816(float* c, const uint32_t* a,
                                         uint32_t b0, uint32_t b1) {
    asm volatile(
        "mma.sync.aligned.m16n8k16.row.col.f32.f16.f16.f32 "
        "{%0,%1,%2,%3}, {%4,%5,%6,%7}, {%8,%9}, {%0,%1,%2,%3};"
        : "+f"(c[0]), "+f"(c[1]), "+f"(c[2]), "+f"(c[3])
        : "r"(a[0]), "r"(a[1]), "r"(a[2]), "r"(a[3]), "r"(b0), "r"(b1));
}
// SW64 swizzle for 64-byte rows (8 rows x 64B atom): conflict-free ldmatrix
#define SWZ64(x) ((x) ^ (((x) >> 3) & 0x30))

// ============================================================
// one-time kernels
// ============================================================
__global__ void zero_kernel(float4* __restrict__ out) {
    int i = blockIdx.x * blockDim.x + threadIdx.x;
    float4 z = make_float4(0.f, 0.f, 0.f, 0.f);
    ((float4*)g_m0)[i] = z;
    ((float4*)g_s1)[i] = z;
    ((float4*)g_m1)[i] = z;
    ((float4*)g_s2)[i] = z;
    out[i] = z;
}

// exact 2-way fp16 split + transpose of W [512K x 512N] -> Wt[2][N][K]
template <int WHICH>
__global__ void prep_kernel(const float* __restrict__ Wsrc) {
    int idx = blockIdx.x * blockDim.x + threadIdx.x;  // over 512*512
    int k = idx >> 9, n = idx & 511;
    float w = Wsrc[idx];
    __half hi = __float2half_rn(w);
    __half lo = __float2half_rn(w - __half2float(hi));
    __half (*dst)[512 * 512] = (WHICH == 1) ? g_W1t : g_W2t;
    int t = n * 512 + k;
    dst[0][t] = hi;
    dst[1][t] = lo;
}

__global__ void step0_kernel() {
    int i = blockIdx.x * blockDim.x + threadIdx.x;
    float4 h = ((const float4*)g_h0)[i];
    float4 m = ((const float4*)g_m0)[i];
    m.x = 0.85f * m.x + h.x;  m.y = 0.85f * m.y + h.y;
    m.z = 0.85f * m.z + h.z;  m.w = 0.85f * m.w + h.w;
    float sx = (m.x > 1.f) ? 1.f : 0.f;  m.x = (m.x > 1.f) ? 0.f : m.x;
    float sy = (m.y > 1.f) ? 1.f : 0.f;  m.y = (m.y > 1.f) ? 0.f : m.y;
    float sz = (m.z > 1.f) ? 1.f : 0.f;  m.z = (m.z > 1.f) ? 0.f : m.z;
    float sw = (m.w > 1.f) ? 1.f : 0.f;  m.w = (m.w > 1.f) ? 0.f : m.w;
    ((float4*)g_m0)[i] = m;
    __half2* sp = (__half2*)(g_spk0 + 4 * (size_t)i);
    sp[0] = __floats2half2_rn(sx, sy);
    sp[1] = __floats2half2_rn(sz, sw);
}

// ============================================================
// layer-0 drive: h0 = relu_concat(inputs) @ W0 (fp32, runs once)
// ============================================================
__global__ __launch_bounds__(256)
void gemm0_kernel(const float* __restrict__ Aext, const float* __restrict__ W) {
    constexpr int KT = 8, NK = 256 / KT;
    __shared__ float As[2][KT][128];
    __shared__ float Bs[2][KT][128];
    const int row0 = blockIdx.x * 128, col0 = blockIdx.y * 128;
    const int tid = threadIdx.x;
    const int tx = tid & 15, ty = tid >> 4;
    const int ar = tid >> 1, aq = (tid & 1) * 4;
    const int bk = tid >> 5, bj = (tid & 31) * 4;

    float acc[8][8];
#pragma unroll
    for (int i = 0; i < 8; i++)
#pragma unroll
        for (int j = 0; j < 8; j++) acc[i][j] = 0.f;

    float4 ra, rb;
    auto LOADG = [&](int k0) {
        int kk = k0 + aq;
        if (kk < 128) {
            float4 v = *(const float4*)(Aext + (size_t)(row0 + ar) * 128 + kk);
            ra.x = fmaxf(v.x, 0.f); ra.y = fmaxf(v.y, 0.f);
            ra.z = fmaxf(v.z, 0.f); ra.w = fmaxf(v.w, 0.f);
        } else {
            float4 v = *(const float4*)(Aext + (size_t)(row0 + ar) * 128 + (kk - 128));
            ra.x = fmaxf(-v.x, 0.f); ra.y = fmaxf(-v.y, 0.f);
            ra.z = fmaxf(-v.z, 0.f); ra.w = fmaxf(-v.w, 0.f);
        }
        rb = *(const float4*)(W + (size_t)(k0 + bk) * 512 + col0 + bj);
    };
    auto STORES = [&](int buf) {
        As[buf][aq + 0][ar] = ra.x; As[buf][aq + 1][ar] = ra.y;
        As[buf][aq + 2][ar] = ra.z; As[buf][aq + 3][ar] = ra.w;
        *(float4*)&Bs[buf][bk][bj] = rb;
    };

    LOADG(0); STORES(0); __syncthreads();
    for (int kt = 0; kt < NK; kt++) {
        const int buf = kt & 1;
        if (kt + 1 < NK) LOADG((kt + 1) * KT);
#pragma unroll
        for (int k = 0; k < KT; k++) {
            float4 a0 = *(const float4*)&As[buf][k][ty * 8];
            float4 a1 = *(const float4*)&As[buf][k][ty * 8 + 4];
            float4 b0 = *(const float4*)&Bs[buf][k][tx * 8];
            float4 b1 = *(const float4*)&Bs[buf][k][tx * 8 + 4];
            float av[8] = {a0.x, a0.y, a0.z, a0.w, a1.x, a1.y, a1.z, a1.w};
            float bv[8] = {b0.x, b0.y, b0.z, b0.w, b1.x, b1.y, b1.z, b1.w};
#pragma unroll
            for (int i = 0; i < 8; i++)
#pragma unroll
                for (int j = 0; j < 8; j++) acc[i][j] = fmaf(av[i], bv[j], acc[i][j]);
        }
        if (kt + 1 < NK) STORES(buf ^ 1);
        __syncthreads();
    }
    const int r0 = row0 + ty * 8, c0 = col0 + tx * 8;
#pragma unroll
    for (int i = 0; i < 8; i++) {
        size_t base = (size_t)(r0 + i) * 512 + c0;
        *(float4*)&g_h0[base]     = make_float4(acc[i][0], acc[i][1], acc[i][2], acc[i][3]);
        *(float4*)&g_h0[base + 4] = make_float4(acc[i][4], acc[i][5], acc[i][6], acc[i][7]);
    }
}

// ============================================================
// HMMA GEMM + fused LIF epilogue (register-direct)
// Tile M=128 x N=128; K=512 in 16 chunks of 32; 2 fp16 W-splits.
// 3-stage cp.async pipeline, 24KB/stage (A 8KB + B 2x8KB), SW64 swizzle.
// 8 warps, warp tile 64x32: warp_m = wid&1, warp_n = wid>>1.
// ============================================================
constexpr int STAGE_BYTES = 24576;
constexpr int SMEM_NEED   = 3 * STAGE_BYTES;   // 72KB -> 2 CTAs/SM

template <int MODE>
__global__ __launch_bounds__(256, 2)
void gemm_mma(float* __restrict__ Mext) {
    extern __shared__ char smem[];
    const int tid = threadIdx.x;
    const int wid = tid >> 5, lane = tid & 31;
    const int warp_m = wid & 1, warp_n = wid >> 1;
    const int row0 = blockIdx.x * 128, col0 = blockIdx.y * 128;

    const __half* A = (MODE == 1) ? g_spk0 : g_spk1;
    const __half* W = (MODE == 1) ? &g_W1t[0][0] : &g_W2t[0][0];

    const uint32_t sb = smem_to_u32(smem);

    // ---- async chunk staging: A[128r][32k], B[2][128n][32k], SW64 ----
    auto load_chunk = [&](int c, int s) {
        const uint32_t ap = sb + s * STAGE_BYTES;
        const uint32_t bp = ap + 8192;
        const int k0 = c * 32;
#pragma unroll
        for (int j = 0; j < 2; j++) {                  // A: 512 x 16B
            int i = tid + j * 256;
            int r = i >> 2, q = i & 3;
            cp16(ap + SWZ64(r * 64 + q * 16),
                 A + (size_t)(row0 + r) * 512 + k0 + q * 8);
        }
#pragma unroll
        for (int j = 0; j < 4; j++) {                  // B: 2 x 512 x 16B
            int i = tid + j * 256;
            int sp = i >> 9, rem = i & 511;
            int n = rem >> 2, q = rem & 3;
            cp16(bp + sp * 8192 + SWZ64(n * 64 + q * 16),
                 W + (size_t)sp * 262144 + (size_t)(col0 + n) * 512 + k0 + q * 8);
        }
        CP_COMMIT();
    };

    load_chunk(0, 0);
    load_chunk(1, 1);

    // ---- MODE 2: layer-0 LIF for NEXT step (overlaps pipeline fill) ----
    if (MODE == 2) {
#pragma unroll
        for (int j = 0; j < 16; j++) {
            int v = tid + j * 256;
            int rr = v >> 5, cc = (v & 31) << 2;
            size_t ix = (size_t)(row0 + rr) * 512 + col0 + cc;
            float4 h = *(const float4*)(g_h0 + ix);
            float4 m = *(const float4*)(g_m0 + ix);
            m.x = 0.85f * m.x + h.x;  m.y = 0.85f * m.y + h.y;
            m.z = 0.85f * m.z + h.z;  m.w = 0.85f * m.w + h.w;
            float px = (m.x > 1.f) ? 1.f : 0.f;  m.x = (m.x > 1.f) ? 0.f : m.x;
            float py = (m.y > 1.f) ? 1.f : 0.f;  m.y = (m.y > 1.f) ? 0.f : m.y;
            float pz = (m.z > 1.f) ? 1.f : 0.f;  m.z = (m.z > 1.f) ? 0.f : m.z;
            float pw = (m.w > 1.f) ? 1.f : 0.f;  m.w = (m.w > 1.f) ? 0.f : m.w;
            *(float4*)(g_m0 + ix) = m;
            __half2* sp2 = (__half2*)(g_spk0 + ix);
            sp2[0] = __floats2half2_rn(px, py);
            sp2[1] = __floats2half2_rn(pz, pw);
        }
    }

    float acc[4][4][4];
#pragma unroll
    for (int mt = 0; mt < 4; mt++)
#pragma unroll
        for (int nb = 0; nb < 4; nb++)
#pragma unroll
            for (int e = 0; e < 4; e++) acc[mt][nb][e] = 0.f;

    const int mat = lane >> 3, mrr = lane & 7;

#pragma unroll 1
    for (int c = 0; c < 16; c++) {
        const int s = c % 3;
        if (c < 15) CP_WAIT(1); else CP_WAIT(0);
        __syncthreads();
        if (c + 2 < 16) load_chunk(c + 2, (c + 2) % 3);

        const uint32_t ab = sb + s * STAGE_BYTES;
        const uint32_t bb = ab + 8192;
#pragma unroll
        for (int k16 = 0; k16 < 2; k16++) {
            const int k0 = k16 * 16;
            uint32_t a[4][4];
#pragma unroll
            for (int mt = 0; mt < 4; mt++) {
                int row = warp_m * 64 + mt * 16 + (mat & 1) * 8 + mrr;
                int kk  = k0 + (mat >> 1) * 8;
                ldm4(a[mt][0], a[mt][1], a[mt][2], a[mt][3],
                     ab + SWZ64(row * 64 + kk * 2));
            }
#pragma unroll
            for (int sp = 0; sp < 2; sp++) {
                uint32_t b[2][4];
#pragma unroll
                for (int nt = 0; nt < 2; nt++) {
                    int n  = warp_n * 32 + nt * 16 + (mat >> 1) * 8 + mrr;
                    int kk = k0 + (mat & 1) * 8;
                    ldm4(b[nt][0], b[nt][1], b[nt][2], b[nt][3],
                         bb + sp * 8192 + SWZ64(n * 64 + kk * 2));
                }
#pragma unroll
                for (int mt = 0; mt < 4; mt++)
#pragma unroll
                    for (int nb = 0; nb < 4; nb++)
                        mma16816(acc[mt][nb], a[mt],
                                 b[nb >> 1][(nb & 1) * 2],
                                 b[nb >> 1][(nb & 1) * 2 + 1]);
            }
        }
        __syncthreads();
    }

    // ---- fused LIF epilogue, direct from mma fragments ----
    float* S = (MODE == 1) ? g_s1 : g_s2;
    float* M = (MODE == 1) ? g_m1 : Mext;
    const int er = row0 + warp_m * 64 + (lane >> 2);
    const int ec = col0 + warp_n * 32 + (lane & 3) * 2;
#pragma unroll
    for (int mt = 0; mt < 4; mt++)
#pragma unroll
        for (int nb = 0; nb < 4; nb++)
#pragma unroll
            for (int hrow = 0; hrow < 2; hrow++) {
                size_t ix = (size_t)(er + mt * 16 + hrow * 8) * 512 + ec + nb * 8;
                float2 sv = *(const float2*)(S + ix);
                float2 mv = *(const float2*)(M + ix);
                float hx = acc[mt][nb][hrow * 2 + 0];
                float hy = acc[mt][nb][hrow * 2 + 1];
                sv.x = 0.9f * sv.x + hx;  mv.x = 0.85f * mv.x + sv.x;
                sv.y = 0.9f * sv.y + hy;  mv.y = 0.85f * mv.y + sv.y;
                if (MODE == 1) {
                    float px = (mv.x > 1.f) ? 1.f : 0.f;  mv.x = (mv.x > 1.f) ? 0.f : mv.x;
                    float py = (mv.y > 1.f) ? 1.f : 0.f;  mv.y = (mv.y > 1.f) ? 0.f : mv.y;
                    *(__half2*)(g_spk1 + ix) = __floats2half2_rn(px, py);
                }
                *(float2*)(S + ix) = sv;
                *(float2*)(M + ix) = mv;
            }
}

// ============================================================
// launch
// ============================================================
extern "C" void kernel_launch(void* const* d_in, const int* in_sizes, int n_in,
                              void* d_out, int out_size) {
    (void)in_sizes; (void)n_in; (void)out_size;
    const float* inp = (const float*)d_in[0];   // [16384, 128]
    const float* W0  = (const float*)d_in[1];   // [256, 512]
    const float* W1  = (const float*)d_in[2];   // [512, 512]
    const float* W2  = (const float*)d_in[3];   // [512, 512]
    float* out = (float*)d_out;                 // m2 state [16384, 512]

    cudaFuncSetAttribute(gemm_mma<1>, cudaFuncAttributeMaxDynamicSharedMemorySize, SMEM_NEED);
    cudaFuncSetAttribute(gemm_mma<2>, cudaFuncAttributeMaxDynamicSharedMemorySize, SMEM_NEED);

    const int EW_BLOCKS = (NELEM / 4) / 256;    // 8192

    zero_kernel<<<EW_BLOCKS, 256>>>((float4*)out);
    prep_kernel<1><<<1024, 256>>>(W1);
    prep_kernel<2><<<1024, 256>>>(W2);
    gemm0_kernel<<<dim3(128, 4), 256>>>(inp, W0);
    step0_kernel<<<EW_BLOCKS, 256>>>();

    dim3 grid(128, 4);
    for (int t = 0; t < NSTEP; t++) {
        gemm_mma<1><<<grid, 256, SMEM_NEED>>>(nullptr);
        gemm_mma<2><<<grid, 256, SMEM_NEED>>>(out);
    }
}